// round 6
// baseline (speedup 1.0000x reference)
#include <cuda_runtime.h>
#include <cstdint>

// Dims: Nt=64, Nr=64, Mt=32, Mr=32, G^2=4096, num_sc=32, B=64, R=8, N_r_RF=4
#define G2 4096
typedef unsigned long long u64;

// ---- device globals (no allocation allowed) ----
// Dual-form tables (scaled 1/8):
//   g_W4[d*32+m] = (w.x, w.x, w.y, -w.y)   conj form:  acc += wxx*k + wyn*swap(k)
//   g_F4[c*32+a] = (f.x, f.x, -f.y, f.y)   mul  form
__device__ float4 g_W4[2048];
__device__ float4 g_F4[2048];
__device__ float2 g_S [(size_t)2048 * 4096];        // S[c*32+bp][g], 64 MB
__device__ float2 g_G1[(size_t)2048 * 2048];        // G1[b*32+m][c*32+s], 32 MB

// ---- f32x2 packed helpers ----
__device__ __forceinline__ u64 ffma2(u64 a, u64 b, u64 c) {
    u64 d; asm("fma.rn.f32x2 %0,%1,%2,%3;" : "=l"(d) : "l"(a), "l"(b), "l"(c)); return d;
}
__device__ __forceinline__ u64 fadd2(u64 a, u64 b) {
    u64 d; asm("add.rn.f32x2 %0,%1,%2;" : "=l"(d) : "l"(a), "l"(b)); return d;
}
__device__ __forceinline__ u64 swap2(u64 v) {
    uint2 t; asm("mov.b64 {%0,%1},%2;" : "=r"(t.x), "=r"(t.y) : "l"(v));
    u64 r;  asm("mov.b64 %0,{%1,%2};" : "=l"(r) : "r"(t.y), "r"(t.x));
    return r;
}
__device__ __forceinline__ uint32_t saddr(const void* p) {
    return (uint32_t)__cvta_generic_to_shared(p);
}
__device__ __forceinline__ void lds_v2(u64& a, u64& b, uint32_t addr) {
    asm volatile("ld.shared.v2.b64 {%0,%1},[%2];" : "=l"(a), "=l"(b) : "r"(addr));
}
__device__ __forceinline__ void ldg_v2(u64& a, u64& b, const void* p) {
    asm("ld.global.nc.v2.b64 {%0,%1},[%2];" : "=l"(a), "=l"(b) : "l"(p));
}
__device__ __forceinline__ void ldg_v2_c(u64& a, u64& b, const void* p) {
    asm volatile("ld.global.v2.b64 {%0,%1},[%2];" : "=l"(a), "=l"(b) : "l"(p));
}
__device__ __forceinline__ void stg_v2(void* p, u64 a, u64 b) {
    asm volatile("st.global.v2.b64 [%0],{%1,%2};" :: "l"(p), "l"(a), "l"(b));
}
__device__ __forceinline__ void ldg4(u64* k, const float2* p) {
    ldg_v2(k[0], k[1], p);
    ldg_v2(k[2], k[3], p + 2);
}

// ---- setup ----
__global__ void setup_kernel(const float* __restrict__ kW, const float* __restrict__ kF) {
    int i = blockIdx.x * blockDim.x + threadIdx.x;
    if (i < 2048) {
        float s, c;
        sincosf(kW[i], &s, &c);
        c *= 0.125f; s *= 0.125f;
        g_W4[i] = make_float4(c, c, s, -s);     // conj form
        sincosf(kF[i], &s, &c);
        c *= 0.125f; s *= 0.125f;
        g_F4[i] = make_float4(c, c, -s, s);     // mul form
    }
}

// =====================================================================
// Core: thread tile = 8 rows x 4 cols, reduce over 64.
// Per step: 4 LDS.v2(16B) + 2 LDG.v2(32B) + 4 swaps + 64 FFMA2.
// Single accumulators (inline swap): acc[8][4] u64.
// WADDR: shared base already offset by row-group; row i at +i*16, step dd at +dd*512.
// =====================================================================
#define CORE_LOOP(PTR, STRIDE, WADDR)                                        \
    u64 acc[8][4];                                                           \
    _Pragma("unroll")                                                        \
    for (int i = 0; i < 8; ++i)                                              \
        _Pragma("unroll")                                                    \
        for (int q = 0; q < 4; ++q) acc[i][q] = 0ull;                        \
    u64 ka[4];                                                               \
    ldg4(ka, PTR);                                                           \
    _Pragma("unroll 2")                                                      \
    for (int dd = 0; dd < 64; ++dd) {                                        \
        u64 kn[4] = {0ull, 0ull, 0ull, 0ull};                                \
        if (dd + 1 < 64) ldg4(kn, PTR + (size_t)(dd + 1) * (STRIDE));        \
        u64 ks[4];                                                           \
        _Pragma("unroll")                                                    \
        for (int q = 0; q < 4; ++q) ks[q] = swap2(ka[q]);                    \
        _Pragma("unroll")                                                    \
        for (int i = 0; i < 8; ++i) {                                        \
            u64 wxx, wyn;                                                    \
            lds_v2(wxx, wyn, (WADDR) + (uint32_t)dd * 512 + i * 16);         \
            _Pragma("unroll")                                                \
            for (int q = 0; q < 4; ++q)                                      \
                acc[i][q] = ffma2(wyn, ks[q], ffma2(wxx, ka[q], acc[i][q])); \
        }                                                                    \
        _Pragma("unroll")                                                    \
        for (int q = 0; q < 4; ++q) ka[q] = kn[q];                           \
    }

#define LOAD_TABLE(DST, SRC)                                                 \
    _Pragma("unroll")                                                        \
    for (int i = 0; i < 8; ++i) DST[threadIdx.x + 256 * i] = SRC[threadIdx.x + 256 * i]; \
    __syncthreads();

// =====================================================================
// sA: S[c*32+bp][g] = sum_d conj(W[d,bp]) * K[c*64+d][g]
// grid 1024 = (c=64, gt=16); 256 thr; tile 8bp x 4g (g-tile 256).
// =====================================================================
__global__ void __launch_bounds__(256) sA_kernel(const float2* __restrict__ K) {
    __shared__ float4 Wt[2048];
    LOAD_TABLE(Wt, g_W4)

    const int t = threadIdx.x;
    const int c = blockIdx.x >> 4, gt = blockIdx.x & 15;
    const int gp = t & 63, bg = t >> 6;
    const int g = gt * 256 + gp * 4;

    const float2* Kp = K + (size_t)(c * 64) * G2 + g;
    const uint32_t waddr = saddr(Wt) + (uint32_t)bg * 128;

    CORE_LOOP(Kp, G2, waddr)

#pragma unroll
    for (int i = 0; i < 8; ++i) {
        float2* Sp = g_S + (size_t)(c * 32 + bg * 8 + i) * G2 + g;
        stg_v2(Sp,     acc[i][0], acc[i][1]);
        stg_v2(Sp + 2, acc[i][2], acc[i][3]);
    }
}

// =====================================================================
// phiB: Phi[(a*32+bp)][g] = sum_c F[c,a] * S[c*32+bp][g]
// grid 512 = (bp=32, gt=16); tile 8a x 4g.
// =====================================================================
__global__ void __launch_bounds__(256) phiB_kernel(float2* __restrict__ Phi) {
    __shared__ float4 Ft[2048];
    LOAD_TABLE(Ft, g_F4)

    const int t = threadIdx.x;
    const int bp = blockIdx.x >> 4, gt = blockIdx.x & 15;
    const int gp = t & 63, ag = t >> 6;
    const int g = gt * 256 + gp * 4;

    const float2* Sp = g_S + (size_t)bp * G2 + g;          // + c*32*G2
    const uint32_t faddr = saddr(Ft) + (uint32_t)ag * 128;

    CORE_LOOP(Sp, (size_t)32 * G2, faddr)

#pragma unroll
    for (int i = 0; i < 8; ++i) {
        float2* Pp = Phi + (size_t)((ag * 8 + i) * 32 + bp) * G2 + g;
        stg_v2(Pp,     acc[i][0], acc[i][1]);
        stg_v2(Pp + 2, acc[i][2], acc[i][3]);
    }
}

// =====================================================================
// y1: G1[b*32+m][cs] = sum_d conj(W[d,m]) * H[b][d][cs]
// grid 512 = (b=64, cst=8); tile 8m x 4cs (cs-tile 256).
// =====================================================================
__global__ void __launch_bounds__(256) y1_kernel(const float2* __restrict__ H) {
    __shared__ float4 Wt[2048];
    LOAD_TABLE(Wt, g_W4)

    const int t = threadIdx.x;
    const int b = blockIdx.x >> 3, cst = blockIdx.x & 7;
    const int csp = t & 63, mg = t >> 6;
    const int cs = cst * 256 + csp * 4;

    const float2* Hp = H + (size_t)b * 131072 + cs;        // + d*2048
    const uint32_t waddr = saddr(Wt) + (uint32_t)mg * 128;

    CORE_LOOP(Hp, 2048, waddr)

#pragma unroll
    for (int i = 0; i < 8; ++i) {
        float2* Gp = g_G1 + (size_t)(b * 32 + mg * 8 + i) * 2048 + cs;
        stg_v2(Gp,     acc[i][0], acc[i][1]);
        stg_v2(Gp + 2, acc[i][2], acc[i][3]);
    }
}

// =====================================================================
// y2s: Y[b][(a*32+m)][s] = sum_c F[c,a] * G1[b*32+m][c*32+s]
// grid 256: 8 (b,m) per block; per (b,m) 32 thr = 8 s-quads x 4 a-groups;
// tile 8a x 4s.
// =====================================================================
__global__ void __launch_bounds__(256) y2s_kernel(float2* __restrict__ Y) {
    __shared__ float4 Ft[2048];
    LOAD_TABLE(Ft, g_F4)

    const int t = threadIdx.x;
    const int bm = blockIdx.x * 8 + (t >> 5);
    const int b = bm >> 5, m = bm & 31;
    const int sub = t & 31;
    const int sp = sub & 7, ag = sub >> 3;
    const int s = sp * 4;

    const float2* Gp = g_G1 + (size_t)bm * 2048 + s;       // + c*32
    const uint32_t faddr = saddr(Ft) + (uint32_t)ag * 128;

    CORE_LOOP(Gp, 32, faddr)

#pragma unroll
    for (int i = 0; i < 8; ++i) {
        float2* yp = Y + (size_t)(b * 1024 + (ag * 8 + i) * 32 + m) * 32 + s;
        stg_v2(yp,     acc[i][0], acc[i][1]);
        stg_v2(yp + 2, acc[i][2], acc[i][3]);
    }
}

// =====================================================================
// y2n: Y[b][a*32 + r*4 + j][s] += sum_n conj(W[n, r*4+j]) * noise[b,r,n,x]
// x = a*32+s; grid 512 = (b,r); thread owns x-quad (x0 = t*4) and 4 j.
// Pure 256 MB DRAM stream + RMW tail. Runs after y2s.
// =====================================================================
__global__ void __launch_bounds__(256) y2n_kernel(const float2* __restrict__ noise,
                                                  float2* __restrict__ Y) {
    __shared__ float4 Wn[256];   // [n*4+j] = (x,x,y,-y)
    const int t = threadIdx.x;
    const int b = blockIdx.x >> 3, r = blockIdx.x & 7;
    Wn[t] = g_W4[(t >> 2) * 32 + r * 4 + (t & 3)];
    __syncthreads();

    const int x0 = t * 4;
    const uint32_t wn = saddr(Wn);
    const float2* np = noise + (size_t)(b * 8 + r) * 65536 + x0;

    u64 acc[4][4];
#pragma unroll
    for (int j = 0; j < 4; ++j)
#pragma unroll
        for (int q = 0; q < 4; ++q) acc[j][q] = 0ull;

#pragma unroll 4
    for (int n = 0; n < 64; ++n) {
        u64 v[4];
        ldg4(v, np + (size_t)n * 1024);
        const u64 w0 = swap2(v[0]), w1 = swap2(v[1]), w2 = swap2(v[2]), w3 = swap2(v[3]);
#pragma unroll
        for (int j = 0; j < 4; ++j) {
            u64 wxx, wyn;
            lds_v2(wxx, wyn, wn + (uint32_t)((n * 4 + j) << 4));
            acc[j][0] = ffma2(wyn, w0, ffma2(wxx, v[0], acc[j][0]));
            acc[j][1] = ffma2(wyn, w1, ffma2(wxx, v[1], acc[j][1]));
            acc[j][2] = ffma2(wyn, w2, ffma2(wxx, v[2], acc[j][2]));
            acc[j][3] = ffma2(wyn, w3, ffma2(wxx, v[3], acc[j][3]));
        }
    }

    const int a = x0 >> 5, s = x0 & 31;
#pragma unroll
    for (int j = 0; j < 4; ++j) {
        float2* yp = Y + (size_t)(b * 1024 + a * 32 + r * 4 + j) * 32 + s;
        u64 y0, y1, y2, y3;
        ldg_v2_c(y0, y1, yp);
        ldg_v2_c(y2, y3, yp + 2);
        stg_v2(yp,     fadd2(y0, acc[j][0]), fadd2(y1, acc[j][1]));
        stg_v2(yp + 2, fadd2(y2, acc[j][2]), fadd2(y3, acc[j][3]));
    }
}

extern "C" void kernel_launch(void* const* d_in, const int* in_sizes, int n_in,
                              void* d_out, int out_size) {
    const float2* H     = (const float2*)d_in[0];  // (64,64,64,32,2) f32
    const float2* noise = (const float2*)d_in[1];  // (64,8,64,1024,2) f32
    const float*  kW    = (const float*)d_in[2];   // (64,32)
    const float*  kF    = (const float*)d_in[3];   // (64,32)
    const float2* K     = (const float2*)d_in[4];  // (4096,4096,2)

    float2* Phi = (float2*)d_out;                   // 1024*4096 complex
    float2* Y   = Phi + (size_t)1024 * 4096;        // 64*1024*32 complex

    setup_kernel<<<8, 256>>>(kW, kF);
    sA_kernel  <<<1024, 256>>>(K);
    y1_kernel  <<<512, 256>>>(H);
    phiB_kernel<<<512, 256>>>(Phi);
    y2s_kernel <<<256, 256>>>(Y);
    y2n_kernel <<<512, 256>>>(noise, Y);
}